// round 4
// baseline (speedup 1.0000x reference)
#include <cuda_runtime.h>

#define NB 8
#define NS 512
#define ND 512

#define TS 8              // s rows per block
#define TD 16             // d columns per tile iteration
#define ROWS (TS*TD)      // 128 edges per tile
#define XP 36             // smem tile row pitch (floats)
#define NTILES (ND/TD)    // 32

typedef unsigned long long u64;

// packed fp32x2 FMA (Blackwell)
__device__ __forceinline__ u64 fma2(u64 a, u64 b, u64 c) {
    u64 d;
    asm("fma.rn.f32x2 %0, %1, %2, %3;" : "=l"(d) : "l"(a), "l"(b), "l"(c));
    return d;
}
__device__ __forceinline__ float2 unpack2(u64 v) {
    float lo, hi; asm("mov.b64 {%0,%1}, %2;" : "=f"(lo), "=f"(hi) : "l"(v));
    return make_float2(lo, hi);
}

// ---------------- scratch ----------------
__device__ float g_tss[NB*NS*32];
__device__ float g_pes[NB*NS*32];
__device__ float g_tdd[NB*ND*32];
__device__ float g_ped[NB*ND*32];
__device__ float g_numd[NB*ND*32];
__device__ float g_zd[NB*ND];

// no-op: shifts launch indices so ncu (-s 5 -c 1) captures main_kernel
__global__ void marker_kernel() {}

// ---------------- prelude ----------------
__global__ __launch_bounds__(256) void prelude_kernel(
    const float* __restrict__ xs, const float* __restrict__ xd,
    const float* __restrict__ Wss, const float* __restrict__ bss,
    const float* __restrict__ Wdd, const float* __restrict__ bdd,
    const float* __restrict__ Wes, const float* __restrict__ Wed)
{
    __shared__ float sW[4*32*33];
    __shared__ float sxs[8*32], sxd[8*32];
    const int t  = threadIdx.x;
    const int r0 = blockIdx.x * 8;

#pragma unroll
    for (int i = t; i < 1024; i += 256) {
        const int o = i >> 5, e = i & 31;
        const int a = e*33 + o;
        sW[0*1056 + a] = Wss[i];
        sW[1*1056 + a] = Wes[i];
        sW[2*1056 + a] = Wdd[i];
        sW[3*1056 + a] = Wed[i];
    }
    sxs[t] = xs[r0*32 + t];
    sxd[t] = xd[r0*32 + t];
    g_numd[r0*32 + t] = 0.f;
    if (t < 8) g_zd[r0 + t] = 0.f;
    __syncthreads();

    const int rl = t >> 5, o = t & 31;
    float tss = bss[o], pes = 0.f, tdd = bdd[o], ped = 0.f;
#pragma unroll
    for (int e = 0; e < 32; e++) {
        const float a = sxs[rl*32 + e];
        const float c = sxd[rl*32 + e];
        const int  wa = e*33 + o;
        tss += a * sW[0*1056 + wa];
        pes += a * sW[1*1056 + wa];
        tdd += c * sW[2*1056 + wa];
        ped += c * sW[3*1056 + wa];
    }
    const int row = r0 + rl;
    g_tss[row*32 + o] = tss;
    g_pes[row*32 + o] = pes;
    g_tdd[row*32 + o] = tdd;
    g_ped[row*32 + o] = ped;
}

// ---------------- main: single pass over x_e, 1 barrier per 16-d tile ----------------
__global__ __launch_bounds__(256, 2) void main_kernel(
    const float* __restrict__ xe,
    const float* __restrict__ Wee, const float* __restrict__ bee,
    const float* __restrict__ Wse,
    const float* __restrict__ ase, const float* __restrict__ ade,
    float* __restrict__ hs, float* __restrict__ he)
{
    extern __shared__ float dsm[];
    float* sXb = dsm;                    // [3][ROWS*XP]  x_e tiles (triple buffer)
    float* sPb = dsm + 3*ROWS*XP;        // [3][TD*32]    p_ed tiles
    float* sDb = sPb + 3*TD*32;          // [3][ROWS]     exp(l_de) per row

    __shared__ float sWs[ROWS];          // exp(l_se), warp-local use
    __shared__ float sWseT[32*33];
    __shared__ float sAse[32], sAde[32];
    __shared__ float sNs[TS*32];
    __shared__ float sZs[TS];

    const int t    = threadIdx.x;
    const int b    = blockIdx.y;
    const int s0   = blockIdx.x * TS;
    const int w    = t >> 5;             // warp id == s_loc
    const int lane = t & 31;

#pragma unroll
    for (int i = t; i < 1024; i += 256) {
        const int o = i >> 5, e = i & 31;
        sWseT[e*33 + o] = Wse[i];
    }
    if (t < 32) { sAse[t] = ase[t]; sAde[t] = ade[t]; }

    // W_ee row 'lane' packed
    u64 wee2[16];
    {
        const u64* wp = (const u64*)(Wee + lane*32);
#pragma unroll
        for (int k = 0; k < 16; k++) wee2[k] = wp[k];
    }
    const float base_sw = bee[lane] + g_pes[(b*NS + s0 + w)*32 + lane];

    // staging: thread t handles row = t>>1 (= s_loc*16 + d_loc), half h = t&1
    const int row = t >> 1, h = t & 1;
    const float* xsrc = xe + ((size_t)((b*NS + s0 + w)*ND + (row & 15)))*32 + h*16;
    const float* psrc = g_ped + (size_t)(b*ND)*32 + 2*t;

    float4 pf0, pf1, pf2, pf3;
    float2 pfp;

    // prologue: load tile0 -> stage buf0 -> prefetch tile1
    {
        const float4* s = (const float4*)xsrc;
        pf0 = s[0]; pf1 = s[1]; pf2 = s[2]; pf3 = s[3];
        pfp = *(const float2*)psrc;
    }
    int ic = 0, ip = 2, in_ = 1;
    {
        float* dx = sXb + ic*(ROWS*XP) + row*XP + h*16;
        *(float4*)dx = pf0; *(float4*)(dx+4) = pf1;
        *(float4*)(dx+8) = pf2; *(float4*)(dx+12) = pf3;
        *(float2*)(sPb + ic*(TD*32) + 2*t) = pfp;
    }
    {
        const float4* s = (const float4*)(xsrc + TD*32);
        pf0 = s[0]; pf1 = s[1]; pf2 = s[2]; pf3 = s[3];
        pfp = *(const float2*)(psrc + TD*32);
    }
    float nums = 0.f, zs = 0.f;
    __syncthreads();

    for (int dt = 0; dt < NTILES; dt++) {
        float* sXc = sXb + ic*(ROWS*XP);

        // ---- num_d for PREVIOUS tile (cross-warp; data sealed by last barrier) ----
        if (dt > 0) {
            const float* sXp = sXb + ip*(ROWS*XP);
            const float* sDp = sDb + ip*ROWS;
#pragma unroll
            for (int half = 0; half < 2; half++) {
                const int dd = w + half*8;
                float a = 0.f, z = 0.f;
#pragma unroll
                for (int sl = 0; sl < 8; sl++) {
                    const int r2 = sl*TD + dd;
                    const float wv = sDp[r2];
                    a += wv * sXp[r2*XP + lane];
                    z += wv;
                }
                atomicAdd(&g_numd[(b*ND + (dt-1)*TD + dd)*32 + lane], a);
                if (lane == 0) atomicAdd(&g_zd[b*ND + (dt-1)*TD + dd], z);
            }
        }

        // ---- logits for current tile (pair-parallel, warp-local rows) ----
        {
            const float* xr = sXc + row*XP + h*16;
            float p1 = 0.f, p2 = 0.f;
#pragma unroll
            for (int i = 0; i < 16; i++) {
                const float x = xr[i];
                p1 += x * sAse[h*16 + i];
                p2 += x * sAde[h*16 + i];
            }
            p1 += __shfl_xor_sync(0xffffffffu, p1, 1);
            p2 += __shfl_xor_sync(0xffffffffu, p2, 1);
            if (h == 0) {
                sWs[row]            = __expf(p1);  // bias shift-invariant
                sDb[ic*ROWS + row]  = __expf(p2);
            }
        }
        __syncwarp();

        // ---- h_e + num_s fused (all warp-local) ----
        {
            const float* sPc = sPb + ic*(TD*32);
            const size_t obase = ((size_t)((b*NS + s0 + w)*ND + dt*TD))*32 + lane;
#pragma unroll
            for (int rr = 0; rr < TD; rr++) {
                const int r2 = w*TD + rr;
                const ulonglong2* xr = (const ulonglong2*)(sXc + r2*XP);
                u64 aa = 0ull, ab = 0ull;
#pragma unroll
                for (int k = 0; k < 8; k++) {
                    const ulonglong2 xv = xr[k];
                    aa = fma2(xv.x, wee2[2*k+0], aa);
                    ab = fma2(xv.y, wee2[2*k+1], ab);
                }
                const float2 ra = unpack2(aa), rb = unpack2(ab);
                he[obase + (size_t)rr*32] =
                    base_sw + sPc[rr*32 + lane] + ((ra.x + rb.x) + (ra.y + rb.y));
                const float wv = sWs[r2];
                nums += wv * sXc[r2*XP + lane];
                zs   += wv;
            }
        }

        // ---- stage next tile into free buffer; prefetch tile+2 ----
        if (dt + 1 < NTILES) {
            float* dx = sXb + in_*(ROWS*XP) + row*XP + h*16;
            *(float4*)dx = pf0; *(float4*)(dx+4) = pf1;
            *(float4*)(dx+8) = pf2; *(float4*)(dx+12) = pf3;
            *(float2*)(sPb + in_*(TD*32) + 2*t) = pfp;
            if (dt + 2 < NTILES) {
                const float4* s = (const float4*)(xsrc + (size_t)(dt+2)*(TD*32));
                pf0 = s[0]; pf1 = s[1]; pf2 = s[2]; pf3 = s[3];
                pfp = *(const float2*)(psrc + (dt+2)*(TD*32));
            }
        }
        __syncthreads();
        const int tmp = ip; ip = ic; ic = in_; in_ = tmp;
    }

    // ---- final num_d (last tile, buffer ip after rotation) ----
    {
        const float* sXp = sXb + ip*(ROWS*XP);
        const float* sDp = sDb + ip*ROWS;
#pragma unroll
        for (int half = 0; half < 2; half++) {
            const int dd = w + half*8;
            float a = 0.f, z = 0.f;
#pragma unroll
            for (int sl = 0; sl < 8; sl++) {
                const int r2 = sl*TD + dd;
                const float wv = sDp[r2];
                a += wv * sXp[r2*XP + lane];
                z += wv;
            }
            atomicAdd(&g_numd[(b*ND + (NTILES-1)*TD + dd)*32 + lane], a);
            if (lane == 0) atomicAdd(&g_zd[b*ND + (NTILES-1)*TD + dd], z);
        }
    }

    // ---- h_s epilogue ----
    sNs[w*32 + lane] = nums;
    if (lane == 0) sZs[w] = zs;
    __syncthreads();
    {
        float acc = 0.f;
#pragma unroll
        for (int e = 0; e < 32; e++)
            acc += sNs[w*32 + e] * sWseT[e*33 + lane];
        const int rg = b*NS + s0 + w;
        hs[rg*32 + lane] = g_tss[rg*32 + lane] + acc / sZs[w];
    }
}

// ---------------- finalize h_d ----------------
__global__ __launch_bounds__(256) void hd_kernel(
    const float* __restrict__ Wde, float* __restrict__ hd)
{
    __shared__ float sWdeT[32*33];
    __shared__ float sNd[8*32];
    __shared__ float sZd[8];
    const int t  = threadIdx.x;
    const int r0 = blockIdx.x * 8;
#pragma unroll
    for (int i = t; i < 1024; i += 256) {
        const int o = i >> 5, e = i & 31;
        sWdeT[e*33 + o] = Wde[i];
    }
    sNd[t] = g_numd[r0*32 + t];
    if (t < 8) sZd[t] = g_zd[r0 + t];
    __syncthreads();

    const int rl = t >> 5, o = t & 31;
    float acc = 0.f;
#pragma unroll
    for (int e = 0; e < 32; e++)
        acc += sNd[rl*32 + e] * sWdeT[e*33 + o];
    const int row = r0 + rl;
    hd[row*32 + o] = g_tdd[row*32 + o] + acc / sZd[rl];
}

// ---------------- launch ----------------
extern "C" void kernel_launch(void* const* d_in, const int* in_sizes, int n_in,
                              void* d_out, int out_size)
{
    const float* xs  = (const float*)d_in[0];
    const float* xd  = (const float*)d_in[1];
    const float* xe  = (const float*)d_in[2];
    const float* Wss = (const float*)d_in[3];
    const float* bss = (const float*)d_in[4];
    const float* Wse = (const float*)d_in[5];
    const float* ase = (const float*)d_in[6];
    const float* Wdd = (const float*)d_in[8];
    const float* bdd = (const float*)d_in[9];
    const float* Wde = (const float*)d_in[10];
    const float* ade = (const float*)d_in[11];
    const float* Wee = (const float*)d_in[13];
    const float* bee = (const float*)d_in[14];
    const float* Wes = (const float*)d_in[15];
    const float* Wed = (const float*)d_in[16];

    float* hs = (float*)d_out;
    float* hd = hs + NB*NS*32;
    float* he = hd + NB*ND*32;

    const int dsm_bytes = (3*ROWS*XP + 3*TD*32 + 3*ROWS) * 4;  // 62976
    static int configured = 0;
    if (!configured) {
        cudaFuncSetAttribute(main_kernel,
            cudaFuncAttributeMaxDynamicSharedMemorySize, dsm_bytes);
        configured = 1;
    }

    marker_kernel<<<1, 32>>>();

    prelude_kernel<<<NB*NS/8, 256>>>(xs, xd, Wss, bss, Wdd, bdd, Wes, Wed);

    dim3 grid(NS/TS, NB);
    main_kernel<<<grid, 256, dsm_bytes>>>(xe, Wee, bee, Wse, ase, ade, hs, he);

    hd_kernel<<<NB*ND/8, 256>>>(Wde, hd);
}

// round 5
// speedup vs baseline: 1.0030x; 1.0030x over previous
#include <cuda_runtime.h>

#define NB 8
#define NS 512
#define ND 512

#define TS 8              // s rows per block
#define TD 16             // d columns per tile iteration
#define ROWS (TS*TD)      // 128 edges per tile
#define XP 36             // smem tile row pitch (floats)
#define NTILES (ND/TD)    // 32

typedef unsigned long long u64;

// packed fp32x2 FMA (Blackwell)
__device__ __forceinline__ u64 fma2(u64 a, u64 b, u64 c) {
    u64 d;
    asm("fma.rn.f32x2 %0, %1, %2, %3;" : "=l"(d) : "l"(a), "l"(b), "l"(c));
    return d;
}
__device__ __forceinline__ float2 unpack2(u64 v) {
    float lo, hi; asm("mov.b64 {%0,%1}, %2;" : "=f"(lo), "=f"(hi) : "l"(v));
    return make_float2(lo, hi);
}

// ---------------- scratch ----------------
__device__ float g_tss[NB*NS*32];
__device__ float g_pes[NB*NS*32];
__device__ float g_tdd[NB*ND*32];
__device__ float g_ped[NB*ND*32];
__device__ float g_numd[NB*ND*32];
__device__ float g_zd[NB*ND];

// no-op: shifts launch indices so ncu (-s 5 -c 1) captures main_kernel
__global__ void marker_kernel() {}

// ---------------- prelude ----------------
__global__ __launch_bounds__(256) void prelude_kernel(
    const float* __restrict__ xs, const float* __restrict__ xd,
    const float* __restrict__ Wss, const float* __restrict__ bss,
    const float* __restrict__ Wdd, const float* __restrict__ bdd,
    const float* __restrict__ Wes, const float* __restrict__ Wed)
{
    __shared__ float sW[4*32*33];
    __shared__ float sxs[8*32], sxd[8*32];
    const int t  = threadIdx.x;
    const int r0 = blockIdx.x * 8;

#pragma unroll
    for (int i = t; i < 1024; i += 256) {
        const int o = i >> 5, e = i & 31;
        const int a = e*33 + o;
        sW[0*1056 + a] = Wss[i];
        sW[1*1056 + a] = Wes[i];
        sW[2*1056 + a] = Wdd[i];
        sW[3*1056 + a] = Wed[i];
    }
    sxs[t] = xs[r0*32 + t];
    sxd[t] = xd[r0*32 + t];
    g_numd[r0*32 + t] = 0.f;
    if (t < 8) g_zd[r0 + t] = 0.f;
    __syncthreads();

    const int rl = t >> 5, o = t & 31;
    float tss = bss[o], pes = 0.f, tdd = bdd[o], ped = 0.f;
#pragma unroll
    for (int e = 0; e < 32; e++) {
        const float a = sxs[rl*32 + e];
        const float c = sxd[rl*32 + e];
        const int  wa = e*33 + o;
        tss += a * sW[0*1056 + wa];
        pes += a * sW[1*1056 + wa];
        tdd += c * sW[2*1056 + wa];
        ped += c * sW[3*1056 + wa];
    }
    const int row = r0 + rl;
    g_tss[row*32 + o] = tss;
    g_pes[row*32 + o] = pes;
    g_tdd[row*32 + o] = tdd;
    g_ped[row*32 + o] = ped;
}

// ---------------- main: single pass over x_e, 1 barrier per 16-d tile ----------------
__global__ __launch_bounds__(256, 2) void main_kernel(
    const float* __restrict__ xe,
    const float* __restrict__ Wee, const float* __restrict__ bee,
    const float* __restrict__ Wse,
    const float* __restrict__ ase, const float* __restrict__ ade,
    float* __restrict__ hs, float* __restrict__ he)
{
    extern __shared__ float dsm[];
    float* sXb = dsm;                    // [3][ROWS*XP]  x_e tiles (triple buffer)
    float* sPb = dsm + 3*ROWS*XP;        // [3][TD*32]    p_ed tiles
    float* sDb = sPb + 3*TD*32;          // [3][ROWS]     exp(l_de) per row

    __shared__ float sWs[ROWS];          // exp(l_se), warp-local use
    __shared__ float sWseT[32*33];
    __shared__ float sAse[32], sAde[32];
    __shared__ float sNs[TS*32];
    __shared__ float sZs[TS];

    const int t    = threadIdx.x;
    const int b    = blockIdx.y;
    const int s0   = blockIdx.x * TS;
    const int w    = t >> 5;             // warp id == s_loc
    const int lane = t & 31;

#pragma unroll
    for (int i = t; i < 1024; i += 256) {
        const int o = i >> 5, e = i & 31;
        sWseT[e*33 + o] = Wse[i];
    }
    if (t < 32) { sAse[t] = ase[t]; sAde[t] = ade[t]; }

    // W_ee row 'lane' packed
    u64 wee2[16];
    {
        const u64* wp = (const u64*)(Wee + lane*32);
#pragma unroll
        for (int k = 0; k < 16; k++) wee2[k] = wp[k];
    }
    const float base_sw = bee[lane] + g_pes[(b*NS + s0 + w)*32 + lane];

    // staging: thread t handles row = t>>1 (= s_loc*16 + d_loc), half h = t&1
    const int row = t >> 1, h = t & 1;
    const float* xsrc = xe + ((size_t)((b*NS + s0 + w)*ND + (row & 15)))*32 + h*16;
    const float* psrc = g_ped + (size_t)(b*ND)*32 + 2*t;

    float4 pf0, pf1, pf2, pf3;
    float2 pfp;

    // prologue: load tile0 -> stage buf0 -> prefetch tile1
    {
        const float4* s = (const float4*)xsrc;
        pf0 = s[0]; pf1 = s[1]; pf2 = s[2]; pf3 = s[3];
        pfp = *(const float2*)psrc;
    }
    int ic = 0, ip = 2, in_ = 1;
    {
        float* dx = sXb + ic*(ROWS*XP) + row*XP + h*16;
        *(float4*)dx = pf0; *(float4*)(dx+4) = pf1;
        *(float4*)(dx+8) = pf2; *(float4*)(dx+12) = pf3;
        *(float2*)(sPb + ic*(TD*32) + 2*t) = pfp;
    }
    {
        const float4* s = (const float4*)(xsrc + TD*32);
        pf0 = s[0]; pf1 = s[1]; pf2 = s[2]; pf3 = s[3];
        pfp = *(const float2*)(psrc + TD*32);
    }
    float nums = 0.f, zs = 0.f;
    __syncthreads();

    for (int dt = 0; dt < NTILES; dt++) {
        float* sXc = sXb + ic*(ROWS*XP);

        // ---- num_d for PREVIOUS tile (cross-warp; data sealed by last barrier) ----
        if (dt > 0) {
            const float* sXp = sXb + ip*(ROWS*XP);
            const float* sDp = sDb + ip*ROWS;
#pragma unroll
            for (int half = 0; half < 2; half++) {
                const int dd = w + half*8;
                float a = 0.f, z = 0.f;
#pragma unroll
                for (int sl = 0; sl < 8; sl++) {
                    const int r2 = sl*TD + dd;
                    const float wv = sDp[r2];
                    a += wv * sXp[r2*XP + lane];
                    z += wv;
                }
                atomicAdd(&g_numd[(b*ND + (dt-1)*TD + dd)*32 + lane], a);
                if (lane == 0) atomicAdd(&g_zd[b*ND + (dt-1)*TD + dd], z);
            }
        }

        // ---- logits for current tile (pair-parallel, warp-local rows) ----
        {
            const float* xr = sXc + row*XP + h*16;
            float p1 = 0.f, p2 = 0.f;
#pragma unroll
            for (int i = 0; i < 16; i++) {
                const float x = xr[i];
                p1 += x * sAse[h*16 + i];
                p2 += x * sAde[h*16 + i];
            }
            p1 += __shfl_xor_sync(0xffffffffu, p1, 1);
            p2 += __shfl_xor_sync(0xffffffffu, p2, 1);
            if (h == 0) {
                sWs[row]            = __expf(p1);  // bias shift-invariant
                sDb[ic*ROWS + row]  = __expf(p2);
            }
        }
        __syncwarp();

        // ---- h_e + num_s fused (all warp-local) ----
        {
            const float* sPc = sPb + ic*(TD*32);
            const size_t obase = ((size_t)((b*NS + s0 + w)*ND + dt*TD))*32 + lane;
#pragma unroll
            for (int rr = 0; rr < TD; rr++) {
                const int r2 = w*TD + rr;
                const ulonglong2* xr = (const ulonglong2*)(sXc + r2*XP);
                u64 aa = 0ull, ab = 0ull;
#pragma unroll
                for (int k = 0; k < 8; k++) {
                    const ulonglong2 xv = xr[k];
                    aa = fma2(xv.x, wee2[2*k+0], aa);
                    ab = fma2(xv.y, wee2[2*k+1], ab);
                }
                const float2 ra = unpack2(aa), rb = unpack2(ab);
                he[obase + (size_t)rr*32] =
                    base_sw + sPc[rr*32 + lane] + ((ra.x + rb.x) + (ra.y + rb.y));
                const float wv = sWs[r2];
                nums += wv * sXc[r2*XP + lane];
                zs   += wv;
            }
        }

        // ---- stage next tile into free buffer; prefetch tile+2 ----
        if (dt + 1 < NTILES) {
            float* dx = sXb + in_*(ROWS*XP) + row*XP + h*16;
            *(float4*)dx = pf0; *(float4*)(dx+4) = pf1;
            *(float4*)(dx+8) = pf2; *(float4*)(dx+12) = pf3;
            *(float2*)(sPb + in_*(TD*32) + 2*t) = pfp;
            if (dt + 2 < NTILES) {
                const float4* s = (const float4*)(xsrc + (size_t)(dt+2)*(TD*32));
                pf0 = s[0]; pf1 = s[1]; pf2 = s[2]; pf3 = s[3];
                pfp = *(const float2*)(psrc + (dt+2)*(TD*32));
            }
        }
        __syncthreads();
        const int tmp = ip; ip = ic; ic = in_; in_ = tmp;
    }

    // ---- final num_d (last tile, buffer ip after rotation) ----
    {
        const float* sXp = sXb + ip*(ROWS*XP);
        const float* sDp = sDb + ip*ROWS;
#pragma unroll
        for (int half = 0; half < 2; half++) {
            const int dd = w + half*8;
            float a = 0.f, z = 0.f;
#pragma unroll
            for (int sl = 0; sl < 8; sl++) {
                const int r2 = sl*TD + dd;
                const float wv = sDp[r2];
                a += wv * sXp[r2*XP + lane];
                z += wv;
            }
            atomicAdd(&g_numd[(b*ND + (NTILES-1)*TD + dd)*32 + lane], a);
            if (lane == 0) atomicAdd(&g_zd[b*ND + (NTILES-1)*TD + dd], z);
        }
    }

    // ---- h_s epilogue ----
    sNs[w*32 + lane] = nums;
    if (lane == 0) sZs[w] = zs;
    __syncthreads();
    {
        float acc = 0.f;
#pragma unroll
        for (int e = 0; e < 32; e++)
            acc += sNs[w*32 + e] * sWseT[e*33 + lane];
        const int rg = b*NS + s0 + w;
        hs[rg*32 + lane] = g_tss[rg*32 + lane] + acc / sZs[w];
    }
}

// ---------------- finalize h_d ----------------
__global__ __launch_bounds__(256) void hd_kernel(
    const float* __restrict__ Wde, float* __restrict__ hd)
{
    __shared__ float sWdeT[32*33];
    __shared__ float sNd[8*32];
    __shared__ float sZd[8];
    const int t  = threadIdx.x;
    const int r0 = blockIdx.x * 8;
#pragma unroll
    for (int i = t; i < 1024; i += 256) {
        const int o = i >> 5, e = i & 31;
        sWdeT[e*33 + o] = Wde[i];
    }
    sNd[t] = g_numd[r0*32 + t];
    if (t < 8) sZd[t] = g_zd[r0 + t];
    __syncthreads();

    const int rl = t >> 5, o = t & 31;
    float acc = 0.f;
#pragma unroll
    for (int e = 0; e < 32; e++)
        acc += sNd[rl*32 + e] * sWdeT[e*33 + o];
    const int row = r0 + rl;
    hd[row*32 + o] = g_tdd[row*32 + o] + acc / sZd[rl];
}

// ---------------- launch ----------------
extern "C" void kernel_launch(void* const* d_in, const int* in_sizes, int n_in,
                              void* d_out, int out_size)
{
    const float* xs  = (const float*)d_in[0];
    const float* xd  = (const float*)d_in[1];
    const float* xe  = (const float*)d_in[2];
    const float* Wss = (const float*)d_in[3];
    const float* bss = (const float*)d_in[4];
    const float* Wse = (const float*)d_in[5];
    const float* ase = (const float*)d_in[6];
    const float* Wdd = (const float*)d_in[8];
    const float* bdd = (const float*)d_in[9];
    const float* Wde = (const float*)d_in[10];
    const float* ade = (const float*)d_in[11];
    const float* Wee = (const float*)d_in[13];
    const float* bee = (const float*)d_in[14];
    const float* Wes = (const float*)d_in[15];
    const float* Wed = (const float*)d_in[16];

    float* hs = (float*)d_out;
    float* hd = hs + NB*NS*32;
    float* he = hd + NB*ND*32;

    const int dsm_bytes = (3*ROWS*XP + 3*TD*32 + 3*ROWS) * 4;  // 62976
    static int configured = 0;
    if (!configured) {
        cudaFuncSetAttribute(main_kernel,
            cudaFuncAttributeMaxDynamicSharedMemorySize, dsm_bytes);
        configured = 1;
    }

    marker_kernel<<<1, 32>>>();

    prelude_kernel<<<NB*NS/8, 256>>>(xs, xd, Wss, bss, Wdd, bdd, Wes, Wed);

    dim3 grid(NS/TS, NB);
    main_kernel<<<grid, 256, dsm_bytes>>>(xe, Wee, bee, Wse, ase, ade, hs, he);

    hd_kernel<<<NB*ND/8, 256>>>(Wde, hd);
}